// round 5
// baseline (speedup 1.0000x reference)
#include <cuda_runtime.h>

#define BB 32
#define LL 48
#define NN 325
#define DD 128
#define G3 384
#define WP 385                 // padded pitch for transposed weights (conflict-free LDS.32)
#define BN (BB*NN)             // 10400 sequences
#define NSTEP LL
#define SR 16                  // sequences per crew-group
#define SP (SR/2)              // packed f32x2 pairs (8)
#define NCREW 2                // crews (128 thr each) per block
#define NTHR (NCREW*128)

typedef unsigned long long ull;

// gi scratch, layout [l][gate][j][t]  (t fastest => pair stores/loads are contiguous)
__device__ float g_gi[(size_t)NSTEP * 3 * DD * BN];

__device__ __forceinline__ ull pk2(float lo, float hi) {
    ull r; asm("mov.b64 %0, {%1, %2};" : "=l"(r) : "f"(lo), "f"(hi)); return r;
}
__device__ __forceinline__ void upk2(ull v, float& lo, float& hi) {
    asm("mov.b64 {%0, %1}, %2;" : "=f"(lo), "=f"(hi) : "l"(v));
}
__device__ __forceinline__ void fma2(ull& d, ull a, ull b) {
    asm("fma.rn.f32x2 %0, %1, %2, %0;" : "+l"(d) : "l"(a), "l"(b));
}
__device__ __forceinline__ float sigm(float x)  { return 1.f / (1.f + __expf(-x)); }
__device__ __forceinline__ float tanh_(float x) { return 1.f - 2.f / (__expf(2.f*x) + 1.f); }

// Pair-swizzle: value for logical slot s of row k lives at physical slot s ^ (2*(k&7)).
// Keeps (even,odd) pairs intact; logical pair p maps to physical pair p ^ (k&7).
__device__ __forceinline__ int swz(int k, int s) { return s ^ ((k & 7) << 1); }

// ---------------------------------------------------------------------------
// Shared inner product: acc[g][p] += Wt-row(k) x staged-row(k) over k=0..127.
// stage rows are [k][16] floats, pair-swizzled; read as 4x ulonglong2 (LDS.128,
// broadcast); Wt is [k][WP] transposed (3 LDS.32 + 3 pk2 per k).
// ---------------------------------------------------------------------------
__device__ __forceinline__ void dot128(
    const float* __restrict__ Wt, const float* __restrict__ stage, int j,
    ull acc0[SP], ull acc1[SP], ull acc2[SP])
{
    #pragma unroll 1
    for (int k0 = 0; k0 < DD; k0 += 8) {
        #pragma unroll
        for (int u = 0; u < 8; ++u) {
            const int k = k0 + u;
            const float* wr = Wt + k*WP;
            float w0 = wr[j], w1 = wr[j+DD], w2 = wr[j+2*DD];
            ull W0 = pk2(w0, w0), W1 = pk2(w1, w1), W2 = pk2(w2, w2);
            const ulonglong2* hp = (const ulonglong2*)(stage + k*SR);
            ull hv[SP];
            #pragma unroll
            for (int m = 0; m < SP/2; ++m) {
                ulonglong2 v = hp[m];
                hv[2*m] = v.x; hv[2*m+1] = v.y;
            }
            #pragma unroll
            for (int q = 0; q < SP; ++q) {
                const int p = q ^ u;            // un-swizzle: physical q -> logical p
                fma2(acc0[p], W0, hv[q]);
                fma2(acc1[p], W1, hv[q]);
                fma2(acc2[p], W2, hv[q]);
            }
        }
    }
}

// ---------------------------------------------------------------------------
// Kernel 1: gi = X . W_ih^T + b_ih for all (t,l), written to g_gi[l][g][j][t].
// Persistent 148 blocks x 2 crews; group = (l, 16 consecutive t).
// ---------------------------------------------------------------------------
__global__ void __launch_bounds__(NTHR, 1) gi_kernel(
    const float* __restrict__ X, const float* __restrict__ W_ih,
    const float* __restrict__ b_ih)
{
    extern __shared__ float sm[];
    float* Wt = sm;                        // [DD][WP]
    float* xs = sm + DD*WP;                // [NCREW][DD][SR]
    const int tid = threadIdx.x;
    for (int i = tid; i < DD*G3; i += NTHR) {
        int g = i / DD, k = i - g*DD;
        Wt[k*WP + g] = W_ih[i];
    }
    const int crew = tid >> 7;
    const int j    = tid & 127;
    float* myxs = xs + crew * (DD*SR);
    const float b0 = b_ih[j], b1 = b_ih[j+DD], b2 = b_ih[j+2*DD];
    __syncthreads();

    const int NG = (BN/SR) * LL;           // 31200 groups
    const int stride = (int)gridDim.x * NCREW;   // 296; extras=120 (even) => crew-uniform per block
    for (int grp = blockIdx.x*NCREW + crew; grp < NG; grp += stride) {
        const int l  = grp % LL;
        const int t0 = (grp / LL) * SR;
        // Stage 16 x-rows (seq t0..t0+15 at step l), swizzled pairs.
        #pragma unroll
        for (int s = 0; s < SR; ++s) {
            int t = t0 + s;
            int b = t / NN, n = t - b*NN;
            myxs[j*SR + swz(j, s)] = X[(((size_t)(b*LL + l))*NN + n)*DD + j];
        }
        __syncthreads();

        ull acc0[SP], acc1[SP], acc2[SP];
        #pragma unroll
        for (int p = 0; p < SP; ++p) {
            acc0[p] = pk2(b0, b0); acc1[p] = pk2(b1, b1); acc2[p] = pk2(b2, b2);
        }
        dot128(Wt, myxs, j, acc0, acc1, acc2);

        // Store: g_gi[l][g][j][t], acc lane pair = (t0+2p, t0+2p+1) -> raw STG.64
        {
            size_t base = ((size_t)(l*3)*DD + j)*BN + t0;
            ull* o0 = (ull*)(g_gi + base);
            ull* o1 = (ull*)(g_gi + base + (size_t)DD*BN);
            ull* o2 = (ull*)(g_gi + base + (size_t)2*DD*BN);
            #pragma unroll
            for (int p = 0; p < SP; ++p) {
                o0[p] = acc0[p]; o1[p] = acc1[p]; o2[p] = acc2[p];
            }
        }
        __syncthreads();
    }
}

// ---------------------------------------------------------------------------
// Kernel 2: GRU recurrence. 325 blocks x 2 crews, exactly 16 seqs per crew.
// ---------------------------------------------------------------------------
__global__ void __launch_bounds__(NTHR, 1) gru_kernel(
    const float* __restrict__ W_hh, const float* __restrict__ b_hh,
    float* __restrict__ out)
{
    extern __shared__ float sm[];
    float* Wt = sm;                        // [DD][WP]
    float* hs = sm + DD*WP;                // [NCREW][DD][SR]
    const int tid = threadIdx.x;
    for (int i = tid; i < DD*G3; i += NTHR) {
        int g = i / DD, k = i - g*DD;
        Wt[k*WP + g] = W_hh[i];
    }
    const int crew = tid >> 7;
    const int j    = tid & 127;
    float* myh = hs + crew * (DD*SR);
    const float b0 = b_hh[j], b1 = b_hh[j+DD], b2 = b_hh[j+2*DD];
    const int t0 = (blockIdx.x*NCREW + crew) * SR;

    float hreg[SR];
    #pragma unroll
    for (int s = 0; s < SR; ++s) { hreg[s] = 0.f; myh[j*SR + s] = 0.f; }
    __syncthreads();

    for (int l = 0; l < NSTEP; ++l) {
        // Prefetch input-side gates as packed pairs (12x LDG.128), latency
        // hidden behind the k-loop.
        ull gir[SP], giz[SP], gin[SP];
        {
            size_t base = ((size_t)(l*3)*DD + j)*BN + t0;
            const ulonglong2* p0 = (const ulonglong2*)(g_gi + base);
            const ulonglong2* p1 = (const ulonglong2*)(g_gi + base + (size_t)DD*BN);
            const ulonglong2* p2 = (const ulonglong2*)(g_gi + base + (size_t)2*DD*BN);
            #pragma unroll
            for (int m = 0; m < SP/2; ++m) {
                ulonglong2 a = p0[m]; gir[2*m] = a.x; gir[2*m+1] = a.y;
                ulonglong2 b = p1[m]; giz[2*m] = b.x; giz[2*m+1] = b.y;
                ulonglong2 c = p2[m]; gin[2*m] = c.x; gin[2*m+1] = c.y;
            }
        }

        ull acc0[SP], acc1[SP], acc2[SP];
        #pragma unroll
        for (int p = 0; p < SP; ++p) {
            acc0[p] = pk2(b0, b0); acc1[p] = pk2(b1, b1); acc2[p] = pk2(b2, b2);
        }
        dot128(Wt, myh, j, acc0, acc1, acc2);
        __syncthreads();   // all h reads done before overwrite

        #pragma unroll
        for (int p = 0; p < SP; ++p) {
            float hr0, hr1, hz0, hz1, hn0, hn1;
            float ir0, ir1, iz0, iz1, in0, in1;
            upk2(acc0[p], hr0, hr1);  upk2(gir[p], ir0, ir1);
            upk2(acc1[p], hz0, hz1);  upk2(giz[p], iz0, iz1);
            upk2(acc2[p], hn0, hn1);  upk2(gin[p], in0, in1);
            {
                int s = 2*p;
                float r  = sigm(ir0 + hr0);
                float z  = sigm(iz0 + hz0);
                float ng = tanh_(in0 + r*hn0);
                hreg[s]  = (1.f - z)*ng + z*hreg[s];
            }
            {
                int s = 2*p + 1;
                float r  = sigm(ir1 + hr1);
                float z  = sigm(iz1 + hz1);
                float ng = tanh_(in1 + r*hn1);
                hreg[s]  = (1.f - z)*ng + z*hreg[s];
            }
        }
        // Write back h (swizzled slots) and output (coalesced over j).
        #pragma unroll
        for (int s = 0; s < SR; ++s)
            myh[j*SR + swz(j, s)] = hreg[s];
        #pragma unroll
        for (int s = 0; s < SR; ++s)
            out[((size_t)l*BN + (t0 + s))*DD + j] = hreg[s];
        __syncthreads();   // new h visible before next step
    }
}

extern "C" void kernel_launch(void* const* d_in, const int* in_sizes, int n_in,
                              void* d_out, int out_size)
{
    const float* X    = (const float*)d_in[0];
    const float* W_ih = (const float*)d_in[1];
    const float* W_hh = (const float*)d_in[2];
    const float* b_ih = (const float*)d_in[3];
    const float* b_hh = (const float*)d_in[4];
    float* out = (float*)d_out;

    const int smem = (DD*WP + NCREW*DD*SR) * (int)sizeof(float);  // 197120+16384 = 213504 B
    cudaFuncSetAttribute(gi_kernel,  cudaFuncAttributeMaxDynamicSharedMemorySize, smem);
    cudaFuncSetAttribute(gru_kernel, cudaFuncAttributeMaxDynamicSharedMemorySize, smem);

    gi_kernel<<<148, NTHR, smem>>>(X, W_ih, b_ih);
    gru_kernel<<<BN/(NCREW*SR), NTHR, smem>>>(W_hh, b_hh, out);   // 325 blocks x 32 seqs
}

// round 8
// speedup vs baseline: 1.2403x; 1.2403x over previous
#include <cuda_runtime.h>

#define BB 32
#define LL 48
#define NN 325
#define DD 128
#define G3 384
#define WP 385                 // padded pitch for transposed weights (conflict-free)
#define BN (BB*NN)             // 10400 sequences
#define ROWS (BN*LL)           // 499200 gi rows
#define SR 8                   // rows/sequences per crew
#define SP (SR/2)              // packed f32x2 pairs
#define NCREW 5                // crews per block (128 threads each)
#define NTHR (NCREW*128)       // 640

typedef unsigned long long ull;

// Scratch for input-side gate projections: gi[t][l][g], t-major so row r = t*L+l.
__device__ float g_gi[(size_t)ROWS * G3];

__device__ __forceinline__ ull pk2(float lo, float hi) {
    ull r; asm("mov.b64 %0, {%1, %2};" : "=l"(r) : "f"(lo), "f"(hi)); return r;
}
__device__ __forceinline__ void upk2(ull v, float& lo, float& hi) {
    asm("mov.b64 {%0, %1}, %2;" : "=f"(lo), "=f"(hi) : "l"(v));
}
// Packed dual-FMA: d = a*b + d on two f32 lanes (sm_100+).
__device__ __forceinline__ void fma2(ull& d, ull a, ull b) {
    asm("fma.rn.f32x2 %0, %1, %2, %0;" : "+l"(d) : "l"(a), "l"(b));
}
__device__ __forceinline__ float sigm(float x)  { return 1.f / (1.f + __expf(-x)); }
__device__ __forceinline__ float tanh_(float x) { return 1.f - 2.f / (__expf(2.f*x) + 1.f); }

// R1's proven inner product: acc[g][p] += W-col(j..)*stage over k=0..127.
__device__ __forceinline__ void dot128(
    const float* __restrict__ Wt, const float* __restrict__ stage, int j,
    ull acc0[SP], ull acc1[SP], ull acc2[SP])
{
    #pragma unroll 8
    for (int k = 0; k < DD; ++k) {
        const float* wr = Wt + k*WP;
        float w0 = wr[j], w1 = wr[j+DD], w2 = wr[j+2*DD];   // conflict-free LDS
        ull W0 = pk2(w0, w0), W1 = pk2(w1, w1), W2 = pk2(w2, w2);
        const float2* xp = (const float2*)(stage + k*SR);   // 64-bit broadcast
        #pragma unroll
        for (int p = 0; p < SP; ++p) {
            float2 v = xp[p];
            ull xv = pk2(v.x, v.y);
            fma2(acc0[p], W0, xv);
            fma2(acc1[p], W1, xv);
            fma2(acc2[p], W2, xv);
        }
    }
}

// ---------------------------------------------------------------------------
// Kernel 1: gi[r][g] = x_row(r) . W_ih[g,:] + b_ih[g]  for all 499200 rows.
// Persistent 148 blocks x 5 crews. 62400 = 740*84 + 240; 240 % 5 == 0 so trip
// counts are uniform within each block (in-loop __syncthreads is safe).
// ---------------------------------------------------------------------------
__global__ void __launch_bounds__(NTHR, 1) gi_kernel(
    const float* __restrict__ X, const float* __restrict__ W_ih,
    const float* __restrict__ b_ih)
{
    extern __shared__ float sm[];
    float* Wt = sm;                      // [DD][WP]  Wt[k][g] = W_ih[g][k]
    float* xs = sm + DD*WP;              // [NCREW][DD][SR]
    const int tid = threadIdx.x;
    for (int i = tid; i < DD*G3; i += NTHR) {
        int g = i / DD, k = i - g*DD;    // linear over W_ih (coalesced read)
        Wt[k*WP + g] = W_ih[i];
    }
    const int crew = tid >> 7;
    const int j    = tid & 127;
    float* myxs = xs + crew * (DD*SR);
    const float b0 = b_ih[j], b1 = b_ih[j+DD], b2 = b_ih[j+2*DD];
    __syncthreads();

    const int ngroups = ROWS / SR;       // 62400
    for (int grp = blockIdx.x*NCREW + crew; grp < ngroups; grp += (int)gridDim.x*NCREW) {
        const int r0 = grp * SR;
        // Stage 8 x-rows into shared, [k][s] layout for pair-broadcast reads.
        #pragma unroll
        for (int s = 0; s < SR; ++s) {
            int r = r0 + s;
            int t = r / LL, l = r - t*LL;
            int b = t / NN, n = t - b*NN;
            myxs[j*SR + s] = X[(((size_t)(b*LL + l))*NN + n)*DD + j];
        }
        __syncthreads();

        ull acc0[SP], acc1[SP], acc2[SP];
        #pragma unroll
        for (int p = 0; p < SP; ++p) {
            acc0[p] = pk2(b0, b0); acc1[p] = pk2(b1, b1); acc2[p] = pk2(b2, b2);
        }
        dot128(Wt, myxs, j, acc0, acc1, acc2);

        #pragma unroll
        for (int p = 0; p < SP; ++p) {
            float a, c;
            size_t base0 = (size_t)(r0 + 2*p)     * G3;
            size_t base1 = (size_t)(r0 + 2*p + 1) * G3;
            upk2(acc0[p], a, c); g_gi[base0 + j]        = a; g_gi[base1 + j]        = c;
            upk2(acc1[p], a, c); g_gi[base0 + DD + j]   = a; g_gi[base1 + DD + j]   = c;
            upk2(acc2[p], a, c); g_gi[base0 + 2*DD + j] = a; g_gi[base1 + 2*DD + j] = c;
        }
        __syncthreads();
    }
}

// ---------------------------------------------------------------------------
// Kernel 2: GRU recurrence. 130 blocks x 5 crews = 650 crews; each crew owns
// exactly 2 groups of 8 sequences for all 48 steps. Single wave, perfectly
// balanced. gi loads happen post-dot (keeps live regs under the 640-thread
// budget); 20 warps/SM hide the latency.
// ---------------------------------------------------------------------------
__global__ void __launch_bounds__(NTHR, 1) gru_kernel(
    const float* __restrict__ W_hh, const float* __restrict__ b_hh,
    float* __restrict__ out)
{
    extern __shared__ float sm[];
    float* Wt = sm;                      // [DD][WP]  W_hh^T
    float* hs = sm + DD*WP;              // [NCREW][DD][SR]
    const int tid = threadIdx.x;
    for (int i = tid; i < DD*G3; i += NTHR) {
        int g = i / DD, k = i - g*DD;
        Wt[k*WP + g] = W_hh[i];
    }
    const int crew = tid >> 7;
    const int j    = tid & 127;
    float* myh = hs + crew * (DD*SR);
    const float b0 = b_hh[j], b1 = b_hh[j+DD], b2 = b_hh[j+2*DD];
    const int crewId = blockIdx.x*NCREW + crew;       // 0..649
    __syncthreads();

    #pragma unroll 1
    for (int gidx = 0; gidx < 2; ++gidx) {
        const int t0 = (crewId + gidx*650) * SR;

        float hreg[SR];
        #pragma unroll
        for (int s = 0; s < SR; ++s) { hreg[s] = 0.f; myh[j*SR + s] = 0.f; }
        __syncthreads();

        for (int l = 0; l < LL; ++l) {
            ull acc0[SP], acc1[SP], acc2[SP];
            #pragma unroll
            for (int p = 0; p < SP; ++p) {
                acc0[p] = pk2(b0, b0); acc1[p] = pk2(b1, b1); acc2[p] = pk2(b2, b2);
            }
            dot128(Wt, myh, j, acc0, acc1, acc2);
            __syncthreads();   // all reads of h done before overwrite

            #pragma unroll
            for (int p = 0; p < SP; ++p) {
                const float* gp0 = g_gi + ((size_t)(t0 + 2*p)*LL + l)*G3;
                const float* gp1 = g_gi + ((size_t)(t0 + 2*p + 1)*LL + l)*G3;
                float hr0, hr1, hz0, hz1, hn0, hn1;
                upk2(acc0[p], hr0, hr1);
                upk2(acc1[p], hz0, hz1);
                upk2(acc2[p], hn0, hn1);
                {
                    int s = 2*p;
                    float r  = sigm(gp0[j] + hr0);
                    float z  = sigm(gp0[j+DD] + hz0);
                    float ng = tanh_(gp0[j+2*DD] + r*hn0);
                    hreg[s]  = (1.f - z)*ng + z*hreg[s];
                }
                {
                    int s = 2*p + 1;
                    float r  = sigm(gp1[j] + hr1);
                    float z  = sigm(gp1[j+DD] + hz1);
                    float ng = tanh_(gp1[j+2*DD] + r*hn1);
                    hreg[s]  = (1.f - z)*ng + z*hreg[s];
                }
            }
            // Write back h ([k][s] layout, thread j owns 8 contiguous floats).
            float4* hp4 = (float4*)(myh + j*SR);
            hp4[0] = make_float4(hreg[0], hreg[1], hreg[2], hreg[3]);
            hp4[1] = make_float4(hreg[4], hreg[5], hreg[6], hreg[7]);
            // Output: out[l][t][j], coalesced.
            #pragma unroll
            for (int s = 0; s < SR; ++s)
                out[((size_t)l*BN + (t0 + s))*DD + j] = hreg[s];
            __syncthreads();   // new h visible before next step's reads
        }
    }
}

extern "C" void kernel_launch(void* const* d_in, const int* in_sizes, int n_in,
                              void* d_out, int out_size)
{
    const float* X    = (const float*)d_in[0];
    const float* W_ih = (const float*)d_in[1];
    const float* W_hh = (const float*)d_in[2];
    const float* b_ih = (const float*)d_in[3];
    const float* b_hh = (const float*)d_in[4];
    float* out = (float*)d_out;

    const int smem = (DD*WP + NCREW*DD*SR) * (int)sizeof(float);  // 197120+20480 = 217600 B
    cudaFuncSetAttribute(gi_kernel,  cudaFuncAttributeMaxDynamicSharedMemorySize, smem);
    cudaFuncSetAttribute(gru_kernel, cudaFuncAttributeMaxDynamicSharedMemorySize, smem);

    gi_kernel<<<148, NTHR, smem>>>(X, W_ih, b_ih);
    gru_kernel<<<130, NTHR, smem>>>(W_hh, b_hh, out);   // 650 crews x 2 groups x 8 seqs
}

// round 9
// speedup vs baseline: 1.4715x; 1.1864x over previous
#include <cuda_runtime.h>

#define BB 32
#define LL 48
#define NN 325
#define DD 128
#define G3 384
#define WP 385                 // padded pitch for transposed weights (conflict-free)
#define BN (BB*NN)             // 10400 sequences
#define ROWS (BN*LL)           // 499200 gi rows
#define SR 8                   // rows/sequences per crew
#define SP (SR/2)              // packed f32x2 pairs
#define NCREW 2                // crews per block (128 threads each)
#define NTHR (NCREW*128)       // 256

typedef unsigned long long ull;

// Scratch for input-side gate projections: gi[t][l][g], t-major so row r = t*L+l.
__device__ float g_gi[(size_t)ROWS * G3];

__device__ __forceinline__ ull pk2(float lo, float hi) {
    ull r; asm("mov.b64 %0, {%1, %2};" : "=l"(r) : "f"(lo), "f"(hi)); return r;
}
__device__ __forceinline__ void upk2(ull v, float& lo, float& hi) {
    asm("mov.b64 {%0, %1}, %2;" : "=f"(lo), "=f"(hi) : "l"(v));
}
// Packed dual-FMA: d = a*b + d on two f32 lanes (sm_100+).
__device__ __forceinline__ void fma2(ull& d, ull a, ull b) {
    asm("fma.rn.f32x2 %0, %1, %2, %0;" : "+l"(d) : "l"(a), "l"(b));
}
__device__ __forceinline__ float sigm(float x)  { return 1.f / (1.f + __expf(-x)); }
__device__ __forceinline__ float tanh_(float x) { return 1.f - 2.f / (__expf(2.f*x) + 1.f); }

// Inner product over k=0..127. Stage rows are 8 floats = 32B, read as two
// LDS.128 (broadcast); lanes are already (even,odd) f32x2 pairs -> zero
// packing MOVs on the stage side. w side: 3 conflict-free LDS.32 + 3 pk2.
// Per k: 5 LDS + 12 FFMA2 (fma pipe is the binding resource).
__device__ __forceinline__ void dot128(
    const float* __restrict__ Wt, const float* __restrict__ stage, int j,
    ull acc0[SP], ull acc1[SP], ull acc2[SP])
{
    #pragma unroll 8
    for (int k = 0; k < DD; ++k) {
        const float* wr = Wt + k*WP;
        float w0 = wr[j], w1 = wr[j+DD], w2 = wr[j+2*DD];
        ull W0 = pk2(w0, w0), W1 = pk2(w1, w1), W2 = pk2(w2, w2);
        const ulonglong2* hp = (const ulonglong2*)(stage + k*SR);  // 16B aligned
        ulonglong2 va = hp[0], vb = hp[1];
        fma2(acc0[0], W0, va.x); fma2(acc1[0], W1, va.x); fma2(acc2[0], W2, va.x);
        fma2(acc0[1], W0, va.y); fma2(acc1[1], W1, va.y); fma2(acc2[1], W2, va.y);
        fma2(acc0[2], W0, vb.x); fma2(acc1[2], W1, vb.x); fma2(acc2[2], W2, vb.x);
        fma2(acc0[3], W0, vb.y); fma2(acc1[3], W1, vb.y); fma2(acc2[3], W2, vb.y);
    }
}

// ---------------------------------------------------------------------------
// Kernel 1: gi[r][g] = x_row(r) . W_ih[g,:] + b_ih[g]  for all 499200 rows.
// Persistent 148 blocks x 2 crews. 62400 = 296*210 + 240; the 240 boundary
// never splits a block's crew pair -> trips uniform within each block.
// ---------------------------------------------------------------------------
__global__ void __launch_bounds__(NTHR, 1) gi_kernel(
    const float* __restrict__ X, const float* __restrict__ W_ih,
    const float* __restrict__ b_ih)
{
    extern __shared__ float sm[];
    float* Wt = sm;                      // [DD][WP]  Wt[k][g] = W_ih[g][k]
    float* xs = sm + DD*WP;              // [NCREW][DD][SR]
    const int tid = threadIdx.x;
    for (int i = tid; i < DD*G3; i += NTHR) {
        int g = i / DD, k = i - g*DD;    // linear over W_ih (coalesced read)
        Wt[k*WP + g] = W_ih[i];
    }
    const int crew = tid >> 7;
    const int j    = tid & 127;
    float* myxs = xs + crew * (DD*SR);
    const float b0 = b_ih[j], b1 = b_ih[j+DD], b2 = b_ih[j+2*DD];
    __syncthreads();

    const int ngroups = ROWS / SR;       // 62400
    for (int grp = blockIdx.x*NCREW + crew; grp < ngroups; grp += (int)gridDim.x*NCREW) {
        const int r0 = grp * SR;
        // Stage 8 x-rows into shared, [k][s] layout for pair-broadcast reads.
        #pragma unroll
        for (int s = 0; s < SR; ++s) {
            int r = r0 + s;
            int t = r / LL, l = r - t*LL;
            int b = t / NN, n = t - b*NN;
            myxs[j*SR + s] = X[(((size_t)(b*LL + l))*NN + n)*DD + j];
        }
        __syncthreads();

        ull acc0[SP], acc1[SP], acc2[SP];
        #pragma unroll
        for (int p = 0; p < SP; ++p) {
            acc0[p] = pk2(b0, b0); acc1[p] = pk2(b1, b1); acc2[p] = pk2(b2, b2);
        }
        dot128(Wt, myxs, j, acc0, acc1, acc2);

        #pragma unroll
        for (int p = 0; p < SP; ++p) {
            float a, c;
            size_t base0 = (size_t)(r0 + 2*p)     * G3;
            size_t base1 = (size_t)(r0 + 2*p + 1) * G3;
            upk2(acc0[p], a, c); g_gi[base0 + j]        = a; g_gi[base1 + j]        = c;
            upk2(acc1[p], a, c); g_gi[base0 + DD + j]   = a; g_gi[base1 + DD + j]   = c;
            upk2(acc2[p], a, c); g_gi[base0 + 2*DD + j] = a; g_gi[base1 + 2*DD + j] = c;
        }
        __syncthreads();
    }
}

// ---------------------------------------------------------------------------
// Kernel 2: GRU recurrence. 650 blocks x 2 crews x 8 seqs, 48 steps in-block.
// h double-buffered in shared -> single barrier per step. gi prefetch at the
// top of each step, hidden behind dot128.
// ---------------------------------------------------------------------------
__global__ void __launch_bounds__(NTHR, 1) gru_kernel(
    const float* __restrict__ W_hh, const float* __restrict__ b_hh,
    float* __restrict__ out)
{
    extern __shared__ float sm[];
    float* Wt = sm;                      // [DD][WP]  W_hh^T
    float* hs = sm + DD*WP;              // [NCREW][2 bufs][DD][SR]
    const int tid = threadIdx.x;
    for (int i = tid; i < DD*G3; i += NTHR) {
        int g = i / DD, k = i - g*DD;
        Wt[k*WP + g] = W_hh[i];
    }
    const int crew = tid >> 7;
    const int j    = tid & 127;
    float* buf0 = hs + crew * (2*DD*SR);
    float* buf1 = buf0 + DD*SR;
    const float b0 = b_hh[j], b1 = b_hh[j+DD], b2 = b_hh[j+2*DD];
    const int t0 = (blockIdx.x*NCREW + crew) * SR;

    float hreg[SR];
    #pragma unroll
    for (int s = 0; s < SR; ++s) { hreg[s] = 0.f; buf0[j*SR + s] = 0.f; }
    __syncthreads();

    for (int l = 0; l < LL; ++l) {
        float* cur = (l & 1) ? buf1 : buf0;
        float* nxt = (l & 1) ? buf0 : buf1;

        // Prefetch input-side gates for this step (hidden behind dot128).
        float gir[SR], giz[SR], gin[SR];
        #pragma unroll
        for (int s = 0; s < SR; ++s) {
            const float* gp = g_gi + ((size_t)(t0 + s)*LL + l)*G3;
            gir[s] = gp[j]; giz[s] = gp[j+DD]; gin[s] = gp[j+2*DD];
        }

        ull acc0[SP], acc1[SP], acc2[SP];
        #pragma unroll
        for (int p = 0; p < SP; ++p) {
            acc0[p] = pk2(b0, b0); acc1[p] = pk2(b1, b1); acc2[p] = pk2(b2, b2);
        }
        dot128(Wt, cur, j, acc0, acc1, acc2);

        #pragma unroll
        for (int p = 0; p < SP; ++p) {
            float hr0, hr1, hz0, hz1, hn0, hn1;
            upk2(acc0[p], hr0, hr1);
            upk2(acc1[p], hz0, hz1);
            upk2(acc2[p], hn0, hn1);
            {
                int s = 2*p;
                float r  = sigm(gir[s] + hr0);
                float z  = sigm(giz[s] + hz0);
                float ng = tanh_(gin[s] + r*hn0);
                hreg[s]  = (1.f - z)*ng + z*hreg[s];
            }
            {
                int s = 2*p + 1;
                float r  = sigm(gir[s] + hr1);
                float z  = sigm(giz[s] + hz1);
                float ng = tanh_(gin[s] + r*hn1);
                hreg[s]  = (1.f - z)*ng + z*hreg[s];
            }
        }
        // Write new h into the other buffer ([k][s] layout, 2x STS.128).
        float4* hp4 = (float4*)(nxt + j*SR);
        hp4[0] = make_float4(hreg[0], hreg[1], hreg[2], hreg[3]);
        hp4[1] = make_float4(hreg[4], hreg[5], hreg[6], hreg[7]);
        // Output: out[l][t][j], coalesced over j.
        #pragma unroll
        for (int s = 0; s < SR; ++s)
            out[((size_t)l*BN + (t0 + s))*DD + j] = hreg[s];
        __syncthreads();   // nxt visible to all warps before next step's dot
    }
}

extern "C" void kernel_launch(void* const* d_in, const int* in_sizes, int n_in,
                              void* d_out, int out_size)
{
    const float* X    = (const float*)d_in[0];
    const float* W_ih = (const float*)d_in[1];
    const float* W_hh = (const float*)d_in[2];
    const float* b_ih = (const float*)d_in[3];
    const float* b_hh = (const float*)d_in[4];
    float* out = (float*)d_out;

    const int smem_gi  = (DD*WP + NCREW*DD*SR)   * (int)sizeof(float);  // 201216 B
    const int smem_gru = (DD*WP + NCREW*2*DD*SR) * (int)sizeof(float);  // 213504 B
    cudaFuncSetAttribute(gi_kernel,  cudaFuncAttributeMaxDynamicSharedMemorySize, smem_gi);
    cudaFuncSetAttribute(gru_kernel, cudaFuncAttributeMaxDynamicSharedMemorySize, smem_gru);

    gi_kernel<<<148, NTHR, smem_gi>>>(X, W_ih, b_ih);
    gru_kernel<<<BN/(NCREW*SR), NTHR, smem_gru>>>(W_hh, b_hh, out);   // 650 blocks
}